// round 14
// baseline (speedup 1.0000x reference)
#include <cuda_runtime.h>

// Inverted index scratch. g_head[row]: 0 = empty, else eid+1.
// g_next[eid]: 0 = end, else next_eid+1.  eid = b*Kp1 + k == output offset.
// g_head is zero at module load; the fused kernel's epilogue resets every
// head it consumed back to 0, so each launch (and graph replay) starts clean.
#define MAX_N (1 << 20)        // >= 1,000,000 rows
#define MAX_E (1 << 21)        // >= 1,048,832 entries
__device__ int g_head[MAX_N];
__device__ int g_next[MAX_E];

// Non-forwardable LDS: compiler cannot CSE this back to the registers that
// produced the stashed value, so the copy-phase register truly dies at the
// stores.
__device__ __forceinline__ float4 lds_f4_fresh(const float4* p) {
    float4 r;
    unsigned saddr = (unsigned)__cvta_generic_to_shared(p);
    asm volatile("ld.shared.v4.f32 {%0,%1,%2,%3}, [%4];"
                 : "=f"(r.x), "=f"(r.y), "=f"(r.z), "=f"(r.w)
                 : "r"(saddr));
    return r;
}

// ----------------------------------------------------------------------------
// Kernel B: bin score entries into per-row chains (eid+1 encoding).
// ----------------------------------------------------------------------------
__global__ void bin_kernel(const int* __restrict__ idx, int Kp1) {
    int k = blockIdx.x * blockDim.x + threadIdx.x;
    int b = blockIdx.y;
    if (k >= Kp1) return;
    int eid = b * Kp1 + k;
    int row = idx[eid];
    g_next[eid] = atomicExch(&g_head[row], eid + 1);
}

// ----------------------------------------------------------------------------
// Kernel C: fused copy + scores + positive momentum update.
// One warp per ONE row. Minimal per-warp footprint (scalar chain state,
// 4KB smem/block) -> 8 blocks/SM -> 64 warps -> occupancy-carried streaming,
// matching the plain-copy profile that reached 80% DRAM.
// Phase 1: LDG.128 row + head load + STG.128 + STS stash (regs die here).
// Phase 2 (65% of warps): walk the avg-1.05-entry chain re-reading the row
//   from smem; momentum rows get an overwriting store; epilogue resets head.
// ----------------------------------------------------------------------------
template <int KP1C, bool EXACT>
__global__ void __launch_bounds__(256, 8)
fused_copy_score_kernel(const float4* __restrict__ mem4,
                        float4* __restrict__ dst4,
                        const float4* __restrict__ x4,
                        float* __restrict__ out,
                        int N, int Kp1_rt, float invT) {
    const int Kp1 = (KP1C > 0) ? KP1C : Kp1_rt;
    const int lane = threadIdx.x & 31;
    const int wlocal = threadIdx.x >> 5;                 // 0..7
    const int r = (blockIdx.x * blockDim.x + threadIdx.x) >> 5;  // one row/warp
    if (!EXACT && r >= N) return;

    // 8 warps x 32 lanes x 16B = 4 KB
    __shared__ float4 stash[8 * 32];
    float4* my = &stash[wlocal * 32 + lane];

    const float4* __restrict__ src = mem4 + (size_t)r * 32 + lane;
    float4*       __restrict__ dst = dst4 + (size_t)r * 32 + lane;

    // ---- Phase 1: copy + stash ----
    int hd;
    {
        float4 v = *src;                                 // LDG.128
        hd = g_head[r];
        *dst = v;                                        // STG.128
        *my = v;                                         // STS.128
    }   // v dead here

    if (hd == 0) return;             // ~35% of rows; head already 0

    // ---- Phase 2: chain walk (avg 1.05 entries) ----
    int posb = -1;
    int ee = hd;
    while (ee > 0) {
        int eid = ee - 1;
        unsigned int b = (unsigned int)eid / (unsigned int)Kp1;
        int k = eid - (int)b * Kp1;
        float4 xv = x4[b * 32 + lane];                   // L1/L2-resident
        float4 rv = lds_f4_fresh(my);
        float s = rv.x * xv.x + rv.y * xv.y
                + rv.z * xv.z + rv.w * xv.w;
        #pragma unroll
        for (int o = 16; o > 0; o >>= 1)
            s += __shfl_xor_sync(0xffffffffu, s, o);
        if (lane == 0) out[eid] = s * invT;
        if (k == 0) posb = max(posb, (int)b);
        ee = g_next[eid];
    }

    // ---- Momentum update overwrite (~256 rows grid-wide) ----
    if (posb >= 0) {
        float4 xv = x4[posb * 32 + lane];
        float4 rv = lds_f4_fresh(my);
        float4 w;
        w.x = 0.5f * rv.x + 0.5f * xv.x;
        w.y = 0.5f * rv.y + 0.5f * xv.y;
        w.z = 0.5f * rv.z + 0.5f * xv.z;
        w.w = 0.5f * rv.w + 0.5f * xv.w;
        float ss = w.x * w.x + w.y * w.y + w.z * w.z + w.w * w.w;
        #pragma unroll
        for (int o = 16; o > 0; o >>= 1)
            ss += __shfl_xor_sync(0xffffffffu, ss, o);
        float inv = 1.0f / sqrtf(ss);
        w.x *= inv; w.y *= inv; w.z *= inv; w.w *= inv;
        *dst = w;
    }

    // ---- Reset this warp's head for the next launch / graph replay ----
    if (lane == 0) g_head[r] = 0;
}

// ----------------------------------------------------------------------------
// Launch. Inputs: x [B,D] f32, memory [N,D] f32, y [B] i32, idx [B,K+1] i32.
// Output: out [B,K+1] f32 then new_memory [N,D] f32.
// ----------------------------------------------------------------------------
extern "C" void kernel_launch(void* const* d_in, const int* in_sizes, int n_in,
                              void* d_out, int out_size) {
    const float* x      = (const float*)d_in[0];
    const float* memory = (const float*)d_in[1];
    const int*   idx    = (const int*)d_in[3];

    int B   = in_sizes[2];                  // 256
    int D   = in_sizes[0] / B;              // 128
    int Kp1 = in_sizes[3] / B;              // 4097
    int N   = in_sizes[1] / D;              // 1,000,000

    float* out_scores = (float*)d_out;
    float* new_memory = (float*)d_out + (long long)in_sizes[3];

    const float invT = 1.0f / 0.07f;

    // B) bin score entries by memory row
    {
        dim3 grid((Kp1 + 255) / 256, B);
        bin_kernel<<<grid, 256>>>(idx, Kp1);
    }

    // C) fused copy + scores + positive update (one warp per row)
    {
        int threads = 256;                           // 8 warps/block
        int rows_per_block = threads / 32;           // 8
        int blocks = (N + rows_per_block - 1) / rows_per_block;
        bool exact = (N % rows_per_block) == 0;      // 1e6 / 8 = 125000 exact
        if (Kp1 == 4097 && exact) {
            fused_copy_score_kernel<4097, true><<<blocks, threads>>>(
                (const float4*)memory, (float4*)new_memory,
                (const float4*)x, out_scores, N, Kp1, invT);
        } else if (exact) {
            fused_copy_score_kernel<0, true><<<blocks, threads>>>(
                (const float4*)memory, (float4*)new_memory,
                (const float4*)x, out_scores, N, Kp1, invT);
        } else {
            fused_copy_score_kernel<0, false><<<blocks, threads>>>(
                (const float4*)memory, (float4*)new_memory,
                (const float4*)x, out_scores, N, Kp1, invT);
        }
    }
}

// round 15
// speedup vs baseline: 1.2053x; 1.2053x over previous
#include <cuda_runtime.h>

// Inverted index scratch. g_head[row]: 0 = empty, else eid+1.
// g_next[eid]: 0 = end, else next_eid+1.  eid = b*Kp1 + k == output offset.
// g_head is zero at module load; the fused kernel's epilogue resets every
// head it consumed back to 0, so each launch (and graph replay) starts clean.
#define MAX_N (1 << 20)        // >= 1,000,000 rows
#define MAX_E (1 << 21)        // >= 1,048,832 entries
__device__ int g_head[MAX_N];
__device__ int g_next[MAX_E];

// Non-forwardable LDS: compiler cannot CSE this back to the registers that
// produced the stashed values, so the copy-phase v[] truly dies at the stores.
__device__ __forceinline__ float4 lds_f4_fresh(const float4* p) {
    float4 r;
    unsigned saddr = (unsigned)__cvta_generic_to_shared(p);
    asm volatile("ld.shared.v4.f32 {%0,%1,%2,%3}, [%4];"
                 : "=f"(r.x), "=f"(r.y), "=f"(r.z), "=f"(r.w)
                 : "r"(saddr));
    return r;
}

// ----------------------------------------------------------------------------
// Kernel B (vectorized): bin score entries into per-row chains.
// Flat eid space: E = B*Kp1 entries, E % 4 == 0, base 16B-aligned.
// One thread: int4 idx load -> 4 atomicExch -> one int4 g_next store.
// ----------------------------------------------------------------------------
__global__ void bin_kernel_vec(const int4* __restrict__ idx4, int E4) {
    int t = blockIdx.x * blockDim.x + threadIdx.x;
    if (t >= E4) return;
    int4 rows = idx4[t];
    int eid = t * 4;
    int4 prev;
    prev.x = atomicExch(&g_head[rows.x], eid + 1);
    prev.y = atomicExch(&g_head[rows.y], eid + 2);
    prev.z = atomicExch(&g_head[rows.z], eid + 3);
    prev.w = atomicExch(&g_head[rows.w], eid + 4);
    *reinterpret_cast<int4*>(&g_next[eid]) = prev;
}

// Scalar fallback for E % 4 != 0 (not hit for this shape).
__global__ void bin_kernel(const int* __restrict__ idx, int E) {
    int eid = blockIdx.x * blockDim.x + threadIdx.x;
    if (eid >= E) return;
    int row = idx[eid];
    g_next[eid] = atomicExch(&g_head[row], eid + 1);
}

// ----------------------------------------------------------------------------
// Kernel C: fused copy + scores + positive momentum update.
// One warp per RPW=2 consecutive rows (proven sweet spot: regs 32, MLP=2,
// chain latency amortized over 2 rows). launch_bounds(256,8) lifts the
// block-residency cap to 8/SM (64 warps) — regs 32 and 8KB smem both fit.
// Phase 1: batched copy stream + smem stash (row regs die at the stores).
// Phase 2: first entries of both rows batched (one interleaved reduction);
//   chains >= 2 take rare serial tails; momentum rows get an overwriting
//   store; epilogue resets heads.
// ----------------------------------------------------------------------------
#define RPW 2

template <int KP1C, bool EXACT>
__global__ void __launch_bounds__(256, 8)
fused_copy_score_kernel(const float4* __restrict__ mem4,
                        float4* __restrict__ dst4,
                        const float4* __restrict__ x4,
                        float* __restrict__ out,
                        int N, int Kp1_rt, float invT) {
    const int Kp1 = (KP1C > 0) ? KP1C : Kp1_rt;
    const int lane = threadIdx.x & 31;
    const int wlocal = threadIdx.x >> 5;                 // 0..7
    const int wg = (blockIdx.x * blockDim.x + threadIdx.x) >> 5;
    const int r0 = wg * RPW;
    if (!EXACT && r0 >= N) return;

    // 8 warps x 2 rows x 32 lanes x 16B = 8 KB
    __shared__ float4 stash[8 * RPW * 32];
    float4* my = &stash[wlocal * (RPW * 32) + lane];

    const float4* __restrict__ src = mem4 + (size_t)r0 * 32 + lane;
    float4*       __restrict__ dst = dst4 + (size_t)r0 * 32 + lane;

    // ---- Phase 1: pure copy stream + smem stash ----
    int hd[RPW];
    {
        float4 v[RPW];
        #pragma unroll
        for (int j = 0; j < RPW; j++) {
            if (EXACT || r0 + j < N) v[j] = src[j * 32];   // LDG.128
        }
        #pragma unroll
        for (int j = 0; j < RPW; j++) {
            hd[j] = (EXACT || r0 + j < N) ? g_head[r0 + j] : 0;
        }
        #pragma unroll
        for (int j = 0; j < RPW; j++) {
            if (EXACT || r0 + j < N) dst[j * 32] = v[j];   // STG.128
        }
        #pragma unroll
        for (int j = 0; j < RPW; j++) {
            my[j * 32] = v[j];                             // STS.128
        }
    }   // v[] dead here

    // ---- Early out only if EVERY row in the group is empty (~12%) ----
    int any = 0;
    #pragma unroll
    for (int j = 0; j < RPW; j++) any |= hd[j];
    if (any == 0) return;            // heads already 0; no reset needed

    int posb[RPW];
    #pragma unroll
    for (int j = 0; j < RPW; j++) posb[j] = -1;

    // ---- First entries: batched, full ILP, single interleaved reduction ----
    int e[RPW], nxt[RPW];
    float s[RPW];
    #pragma unroll
    for (int j = 0; j < RPW; j++) {
        e[j] = hd[j];
        nxt[j] = (e[j] > 0) ? g_next[e[j] - 1] : 0;
    }
    #pragma unroll
    for (int j = 0; j < RPW; j++) {
        if (e[j] > 0) {
            unsigned int b = (unsigned int)(e[j] - 1) / (unsigned int)Kp1;
            float4 xv = x4[b * 32 + lane];                 // L1/L2-resident
            float4 rv = lds_f4_fresh(my + j * 32);         // independent LDS
            s[j] = rv.x * xv.x + rv.y * xv.y
                 + rv.z * xv.z + rv.w * xv.w;
        } else {
            s[j] = 0.0f;
        }
    }
    #pragma unroll
    for (int o = 16; o > 0; o >>= 1) {
        #pragma unroll
        for (int j = 0; j < RPW; j++) {
            s[j] += __shfl_xor_sync(0xffffffffu, s[j], o);
        }
    }
    #pragma unroll
    for (int j = 0; j < RPW; j++) {
        if (e[j] > 0) {
            int eid = e[j] - 1;
            unsigned int b = (unsigned int)eid / (unsigned int)Kp1;
            int k = eid - (int)b * Kp1;
            if (lane == 0) out[eid] = s[j] * invT;
            if (k == 0) posb[j] = max(posb[j], (int)b);
        }
    }

    // ---- Continuation for chains of length >= 2 (rare) ----
    #pragma unroll
    for (int j = 0; j < RPW; j++) {
        int ee = nxt[j];
        while (ee > 0) {
            int eid = ee - 1;
            unsigned int b = (unsigned int)eid / (unsigned int)Kp1;
            int k = eid - (int)b * Kp1;
            float4 xv = x4[b * 32 + lane];
            float4 rv = lds_f4_fresh(my + j * 32);
            float ss = rv.x * xv.x + rv.y * xv.y
                     + rv.z * xv.z + rv.w * xv.w;
            #pragma unroll
            for (int o = 16; o > 0; o >>= 1)
                ss += __shfl_xor_sync(0xffffffffu, ss, o);
            if (lane == 0) out[eid] = ss * invT;
            if (k == 0) posb[j] = max(posb[j], (int)b);
            ee = g_next[eid];
        }
    }

    // ---- Momentum update overwrite (~256 rows grid-wide) ----
    #pragma unroll
    for (int j = 0; j < RPW; j++) {
        if (posb[j] >= 0) {
            float4 xv = x4[posb[j] * 32 + lane];
            float4 rv = lds_f4_fresh(my + j * 32);
            float4 w;
            w.x = 0.5f * rv.x + 0.5f * xv.x;
            w.y = 0.5f * rv.y + 0.5f * xv.y;
            w.z = 0.5f * rv.z + 0.5f * xv.z;
            w.w = 0.5f * rv.w + 0.5f * xv.w;
            float ss = w.x * w.x + w.y * w.y + w.z * w.z + w.w * w.w;
            #pragma unroll
            for (int o = 16; o > 0; o >>= 1)
                ss += __shfl_xor_sync(0xffffffffu, ss, o);
            float inv = 1.0f / sqrtf(ss);
            w.x *= inv; w.y *= inv; w.z *= inv; w.w *= inv;
            dst[j * 32] = w;
        }
    }

    // ---- Reset this warp's heads for the next launch / graph replay ----
    if (lane < RPW) {
        if (EXACT || r0 + lane < N) g_head[r0 + lane] = 0;
    }
}

// ----------------------------------------------------------------------------
// Launch. Inputs: x [B,D] f32, memory [N,D] f32, y [B] i32, idx [B,K+1] i32.
// Output: out [B,K+1] f32 then new_memory [N,D] f32.
// ----------------------------------------------------------------------------
extern "C" void kernel_launch(void* const* d_in, const int* in_sizes, int n_in,
                              void* d_out, int out_size) {
    const float* x      = (const float*)d_in[0];
    const float* memory = (const float*)d_in[1];
    const int*   idx    = (const int*)d_in[3];

    int B   = in_sizes[2];                  // 256
    int D   = in_sizes[0] / B;              // 128
    int Kp1 = in_sizes[3] / B;              // 4097
    int N   = in_sizes[1] / D;              // 1,000,000
    int E   = in_sizes[3];                  // B*Kp1 = 1,048,832

    float* out_scores = (float*)d_out;
    float* new_memory = (float*)d_out + (long long)E;

    const float invT = 1.0f / 0.07f;

    // B) bin score entries by memory row (vectorized when E % 4 == 0)
    if ((E & 3) == 0) {
        int E4 = E >> 2;                    // 262,208
        bin_kernel_vec<<<(E4 + 255) / 256, 256>>>((const int4*)idx, E4);
    } else {
        bin_kernel<<<(E + 255) / 256, 256>>>(idx, E);
    }

    // C) fused copy + scores + positive update
    {
        int threads = 256;                           // 8 warps/block
        int rows_per_block = (threads / 32) * RPW;   // 16
        int blocks = (N + rows_per_block - 1) / rows_per_block;
        bool exact = (N % rows_per_block) == 0;      // 1e6 / 16 = 62500 exact
        if (Kp1 == 4097 && exact) {
            fused_copy_score_kernel<4097, true><<<blocks, threads>>>(
                (const float4*)memory, (float4*)new_memory,
                (const float4*)x, out_scores, N, Kp1, invT);
        } else if (exact) {
            fused_copy_score_kernel<0, true><<<blocks, threads>>>(
                (const float4*)memory, (float4*)new_memory,
                (const float4*)x, out_scores, N, Kp1, invT);
        } else {
            fused_copy_score_kernel<0, false><<<blocks, threads>>>(
                (const float4*)memory, (float4*)new_memory,
                (const float4*)x, out_scores, N, Kp1, invT);
        }
    }
}